// round 1
// baseline (speedup 1.0000x reference)
#include <cuda_runtime.h>

#define F_ 256
#define T_ 128
#define D_ 6
#define U_ 16
#define NB_ 64
#define N_ 768          // T_*D_
#define BROWS 32        // batch rows per CTA
#define CCOLS 192       // 32 trees * 6 cols per chunk
#define NCHUNK 4
#define SEL_LD 200      // padded row stride for sel tile (floats)
#define P_LD 196        // padded row stride for p tile
#define RESP_LD 68      // padded row stride for response tile

// Selector matrix after sparsemax, stored K-major: g_sel[f*768 + t*6 + d]
__device__ float g_sel[F_ * N_];

__device__ __forceinline__ float f4get(const float4& v, int i) {
    return i == 0 ? v.x : (i == 1 ? v.y : (i == 2 ? v.z : v.w));
}

// ---------------------------------------------------------------------------
// Kernel 1: sparsemax over the last axis (D=6) of feature_selection_logits.
// One thread per (f, t) row; reads 6 contiguous floats, writes 6 contiguous.
// ---------------------------------------------------------------------------
__global__ __launch_bounds__(256) void sparsemax_kernel(const float* __restrict__ fsl) {
    int idx = blockIdx.x * blockDim.x + threadIdx.x;   // 0 .. F_*T_-1
    if (idx >= F_ * T_) return;
    const float* zin = fsl + (size_t)idx * D_;
    float z[D_], zs[D_];
#pragma unroll
    for (int d = 0; d < D_; d++) { z[d] = zin[d]; zs[d] = z[d]; }
    // sort descending (fixed-pass bubble, fully unrolled)
#pragma unroll
    for (int i = 0; i < D_; i++) {
#pragma unroll
        for (int j = 0; j < D_ - 1; j++) {
            if (zs[j] < zs[j + 1]) { float t = zs[j]; zs[j] = zs[j + 1]; zs[j + 1] = t; }
        }
    }
    float csum[D_];
    float cs = 0.0f;
#pragma unroll
    for (int k = 0; k < D_; k++) { cs += zs[k]; csum[k] = cs; }
    int kz = 0;
#pragma unroll
    for (int k = 0; k < D_; k++) {
        if (1.0f + (float)(k + 1) * zs[k] > csum[k]) kz++;
    }
    float tau = (csum[kz - 1] - 1.0f) / (float)kz;
    // g_sel[f*768 + t*6 + d] == g_sel[idx*6 + d] since idx = f*T_ + t
    float* outp = g_sel + (size_t)idx * D_;
#pragma unroll
    for (int d = 0; d < D_; d++) outp[d] = fmaxf(z[d] - tau, 0.0f);
}

// ---------------------------------------------------------------------------
// Kernel 2: fused feature GEMM + sparsemoid + oblivious-tree eval + response
// contraction + tree-sum. CTA = 32 batch rows, 256 threads, loops 4 chunks of
// 32 trees.
// ---------------------------------------------------------------------------
__global__ __launch_bounds__(256, 1) void odst_main(
    const float* __restrict__ x,
    const float* __restrict__ thr,
    const float* __restrict__ lt,
    const float* __restrict__ resp,
    float* __restrict__ out)
{
    extern __shared__ float smem[];
    float* x_s    = smem;                        // [32][256]      8192 f
    float* sel_s  = x_s + 32 * 256;              // [64][SEL_LD]  12800 f
    float* p_s    = sel_s + 64 * SEL_LD;         // [32][P_LD]     6272 f
    float* a_s    = p_s + 32 * P_LD;             // [192]
    float* b_s    = a_s + CCOLS;                 // [192]
    float* resp_s = b_s + CCOLS;                 // [8][16][RESP_LD] 8704 f
    float* out_s  = resp_s + 8 * 16 * RESP_LD;   // [32][16]        512 f

    const int tid  = threadIdx.x;
    const int row0 = blockIdx.x * BROWS;

    // zero output accumulation buffer
    out_s[tid] = 0.0f;
    out_s[tid + 256] = 0.0f;

    // load x tile (coalesced float4)
    {
        const float4* xg = (const float4*)(x + (size_t)row0 * F_);
        float4* xs4 = (float4*)x_s;
#pragma unroll
        for (int i = 0; i < 8; i++) xs4[tid + i * 256] = xg[tid + i * 256];
    }

    // eval-phase decomposition: warp -> tree slot, lane -> (row quad, u quad)
    const int w    = tid >> 5;
    const int lane = tid & 31;
    const int rb   = (lane & 7) * 4;    // row base (4 rows)
    const int ub   = (lane >> 3) * 4;   // u base (4 outputs)

    // GEMM-phase decomposition: 4 row groups x 64 col groups, tile 8r x 3c
    const int colg = tid & 63;
    const int rowg = tid >> 6;
    const int c0   = colg * 3;
    const int r0g  = rowg * 8;

    float acc[4][4];
#pragma unroll
    for (int i = 0; i < 4; i++)
#pragma unroll
        for (int j = 0; j < 4; j++) acc[i][j] = 0.0f;

    for (int chunk = 0; chunk < NCHUNK; chunk++) {
        const int nbase = chunk * CCOLS;
        __syncthreads();  // previous chunk's eval fully done; x_s loaded (1st iter)

        if (tid < CCOLS) {
            float e = 0.5f * expf(-lt[nbase + tid]);
            a_s[tid] = e;
            b_s[tid] = 0.5f - e * thr[nbase + tid];
        }

        float fv[8][3];
#pragma unroll
        for (int i = 0; i < 8; i++) { fv[i][0] = 0.f; fv[i][1] = 0.f; fv[i][2] = 0.f; }

        for (int kb = 0; kb < 4; kb++) {
            __syncthreads();
            // stage selector tile: 64 k-rows x 192 cols
            const float* gs = g_sel + (size_t)(kb * 64) * N_ + nbase;
#pragma unroll
            for (int i = 0; i < 12; i++) {
                int q  = tid + i * 256;          // float4 index 0..3071
                int kk = q / 48;
                int cc = (q % 48) * 4;
                *(float4*)&sel_s[kk * SEL_LD + cc] = *(const float4*)&gs[kk * N_ + cc];
            }
            __syncthreads();

            const float* xrow = x_s + r0g * 256 + kb * 64;
#pragma unroll 4
            for (int k = 0; k < 64; k++) {
                const float* sr = sel_s + k * SEL_LD + c0;
                float s0 = sr[0], s1 = sr[1], s2 = sr[2];
#pragma unroll
                for (int i = 0; i < 8; i++) {
                    float xv = xrow[i * 256 + k];   // broadcast within warp
                    fv[i][0] = fmaf(xv, s0, fv[i][0]);
                    fv[i][1] = fmaf(xv, s1, fv[i][1]);
                    fv[i][2] = fmaf(xv, s2, fv[i][2]);
                }
            }
        }

        // sparsemoid: p = clip(0.5*tl + 0.5) = saturate(a*fv + b)
#pragma unroll
        for (int i = 0; i < 8; i++) {
#pragma unroll
            for (int j = 0; j < 3; j++) {
                int cc = c0 + j;
                p_s[(r0g + i) * P_LD + cc] =
                    __saturatef(fmaf(a_s[cc], fv[i][j], b_s[cc]));
            }
        }
        __syncthreads();

        // tree eval: warp w handles tree (chunk*32 + it*8 + w)
        for (int it = 0; it < 4; it++) {
            const int tloc = it * 8 + w;
            const int tg   = chunk * 32 + tloc;
            float* rs = resp_s + w * (16 * RESP_LD);
            // warp-private response staging (16 u x 64 bins)
            {
                const float4* rg = (const float4*)(resp + (size_t)tg * (U_ * NB_));
#pragma unroll
                for (int m = 0; m < 8; m++) {
                    int q  = m * 32 + lane;   // float4 index 0..255
                    int u  = q >> 4;
                    int cq = q & 15;
                    *(float4*)&rs[u * RESP_LD + cq * 4] = rg[q];
                }
            }
            __syncwarp();

            const int pc = tloc * 6;
            float r01[4][4], r23[4][4], r45[4][4];
#pragma unroll
            for (int rr = 0; rr < 4; rr++) {
                const float* pr = p_s + (rb + rr) * P_LD + pc;
                float p0 = pr[0], p1 = pr[1], p2 = pr[2];
                float p3 = pr[3], p4 = pr[4], p5 = pr[5];
                float q0 = 1.0f - p0, q1 = 1.0f - p1, q2 = 1.0f - p2;
                float q3 = 1.0f - p3, q4 = 1.0f - p4, q5 = 1.0f - p5;
                // q_d(bit): bit==0 -> p_d, bit==1 -> 1-p_d ; index j = b0 + 2*b1
                r01[rr][0] = p0 * p1; r01[rr][1] = q0 * p1;
                r01[rr][2] = p0 * q1; r01[rr][3] = q0 * q1;
                r23[rr][0] = p2 * p3; r23[rr][1] = q2 * p3;
                r23[rr][2] = p2 * q3; r23[rr][3] = q2 * q3;
                r45[rr][0] = p4 * p5; r45[rr][1] = q4 * p5;
                r45[rr][2] = p4 * q5; r45[rr][3] = q4 * q5;
            }

#pragma unroll
            for (int j45 = 0; j45 < 4; j45++) {
#pragma unroll
                for (int j23 = 0; j23 < 4; j23++) {
                    float t2[4];
#pragma unroll
                    for (int rr = 0; rr < 4; rr++)
                        t2[rr] = r45[rr][j45] * r23[rr][j23];
                    const int cb = j45 * 16 + j23 * 4;
                    float4 rv0 = *(const float4*)&rs[(ub + 0) * RESP_LD + cb];
                    float4 rv1 = *(const float4*)&rs[(ub + 1) * RESP_LD + cb];
                    float4 rv2 = *(const float4*)&rs[(ub + 2) * RESP_LD + cb];
                    float4 rv3 = *(const float4*)&rs[(ub + 3) * RESP_LD + cb];
#pragma unroll
                    for (int j01 = 0; j01 < 4; j01++) {
                        float rw[4];
#pragma unroll
                        for (int rr = 0; rr < 4; rr++)
                            rw[rr] = t2[rr] * r01[rr][j01];
                        float ev[4];
                        ev[0] = f4get(rv0, j01);
                        ev[1] = f4get(rv1, j01);
                        ev[2] = f4get(rv2, j01);
                        ev[3] = f4get(rv3, j01);
#pragma unroll
                        for (int rr = 0; rr < 4; rr++)
#pragma unroll
                            for (int uu = 0; uu < 4; uu++)
                                acc[rr][uu] = fmaf(rw[rr], ev[uu], acc[rr][uu]);
                    }
                }
            }
            __syncwarp();   // protect rs before next iteration restages it
        }
    }

    // deterministic cross-warp reduction into out_s
    for (int pass = 0; pass < 8; pass++) {
        __syncthreads();
        if (w == pass) {
#pragma unroll
            for (int rr = 0; rr < 4; rr++)
#pragma unroll
                for (int uu = 0; uu < 4; uu++)
                    out_s[(rb + rr) * U_ + ub + uu] += acc[rr][uu];
        }
    }
    __syncthreads();

    // write output: 32 rows x 16 u, coalesced float2
    float2 v = *(float2*)&out_s[tid * 2];
    *(float2*)(out + (size_t)row0 * U_ + tid * 2) = v;
}

// ---------------------------------------------------------------------------
extern "C" void kernel_launch(void* const* d_in, const int* in_sizes, int n_in,
                              void* d_out, int out_size) {
    const float* x    = (const float*)d_in[0];
    const float* fsl  = (const float*)d_in[1];
    const float* thr  = (const float*)d_in[2];
    const float* lt   = (const float*)d_in[3];
    const float* resp = (const float*)d_in[4];
    float* out = (float*)d_out;

    const int smem_bytes =
        (32 * 256 + 64 * SEL_LD + 32 * P_LD + 2 * CCOLS + 8 * 16 * RESP_LD + 512)
        * (int)sizeof(float);   // 147456 B

    cudaFuncSetAttribute(odst_main, cudaFuncAttributeMaxDynamicSharedMemorySize,
                         smem_bytes);

    sparsemax_kernel<<<(F_ * T_) / 256, 256>>>(fsl);
    odst_main<<<(4096 / BROWS), 256, smem_bytes>>>(x, thr, lt, resp, out);
}